// round 11
// baseline (speedup 1.0000x reference)
#include <cuda_runtime.h>

// Torch_SINDy streaming kernel, R11: 256-bit loads (sm_100+ LDG.E.256).
// Plateau at ~76% DRAM across R7-R10. v8.f32 loads: one instruction = 32B
// contiguous per lane, warp covers 1024B -> half the LDG instructions and
// half the L1tex wavefront entries per byte vs LDG.128, with coalescing
// intact (unlike R5's multi-instruction consecutive-row split).
// Each thread owns 2 consecutive rows per item -> paired STG.64 stores.

#define THREADS 128
#define ITEMS2 4                          // 4 x 32B loads per thread
#define CHUNK (THREADS * ITEMS2 * 2)      // 1024 rows per block

struct __align__(32) f8 {
    float x0, x1, x2, x3, x4, x5, x6, x7;
};

__device__ __forceinline__ f8 ldg256_cs(const f8* p) {
    f8 r;
    asm volatile("ld.global.nc.L1::no_allocate.v8.f32 "
                 "{%0,%1,%2,%3,%4,%5,%6,%7}, [%8];"
                 : "=f"(r.x0), "=f"(r.x1), "=f"(r.x2), "=f"(r.x3),
                   "=f"(r.x4), "=f"(r.x5), "=f"(r.x6), "=f"(r.x7)
                 : "l"(p));
    return r;
}

__device__ __forceinline__ float sindy_row4(float u, float y, float z, float w,
                                            const float* c) {
    float u2 = u * u;
    float u3 = u2 * u;
    float r = u * c[0] + u2 * c[1] + u3 * c[2]
            + y * c[3] + z * c[4] + w * c[5];
    r += y * (u * c[6]  + u2 * c[7]  + u3 * c[8]);
    r += z * (u * c[9]  + u2 * c[10] + u3 * c[11]);
    r += w * (u * c[12] + u2 * c[13] + u3 * c[14]);
    return r;
}

__device__ __forceinline__ void load_coeffs(const float* __restrict__ coeff,
                                            const float* __restrict__ base,
                                            float* c) {
    const float4* c4 = (const float4*)coeff;
    const float4* b4 = (const float4*)base;
#pragma unroll
    for (int q = 0; q < 3; ++q) {
        float4 cv = __ldg(&c4[q]);
        float4 bv = __ldg(&b4[q]);
        c[q*4+0] = cv.x * bv.x;
        c[q*4+1] = cv.y * bv.y;
        c[q*4+2] = cv.z * bv.z;
        c[q*4+3] = cv.w * bv.w;
    }
#pragma unroll
    for (int q = 12; q < 15; ++q)
        c[q] = __ldg(&coeff[q]) * __ldg(&base[q]);
}

// Exact path: grid covers n exactly, no guards.
// 4 front-batched LDG.256 (each = 2 rows), then 4 paired STG.64.
__global__ void __launch_bounds__(THREADS)
sindy_kernel_exact(const f8* __restrict__ big_u2,   // [N/2] row-pairs
                   const float* __restrict__ coeff,
                   const float* __restrict__ base,
                   float2* __restrict__ out2) {      // [N/2] result-pairs
    int base2 = blockIdx.x * (THREADS * ITEMS2) + threadIdx.x;

    f8 v[ITEMS2];
#pragma unroll
    for (int k = 0; k < ITEMS2; ++k)
        v[k] = ldg256_cs(&big_u2[base2 + k * THREADS]);

    // Coefficient loads overlap the in-flight data loads.
    float c[15];
    load_coeffs(coeff, base, c);

#pragma unroll
    for (int k = 0; k < ITEMS2; ++k) {
        float2 r;
        r.x = sindy_row4(v[k].x0, v[k].x1, v[k].x2, v[k].x3, c);
        r.y = sindy_row4(v[k].x4, v[k].x5, v[k].x6, v[k].x7, c);
        out2[base2 + k * THREADS] = r;
    }
}

// Guarded tail for arbitrary n (scalar rows).
__global__ void __launch_bounds__(THREADS)
sindy_tail(const float4* __restrict__ big_u,
           const float*  __restrict__ coeff,
           const float*  __restrict__ base,
           float*        __restrict__ out,
           int start, int n) {
    float c[15];
    load_coeffs(coeff, base, c);
    int i = start + blockIdx.x * THREADS + threadIdx.x;
    if (i < n) {
        float4 v = __ldcs(&big_u[i]);
        out[i] = sindy_row4(v.x, v.y, v.z, v.w, c);
    }
}

extern "C" void kernel_launch(void* const* d_in, const int* in_sizes, int n_in,
                              void* d_out, int out_size) {
    const float4* big_u = (const float4*)d_in[0];   // [N,4] f32
    const float*  coeff = (const float*)d_in[1];    // [15]  f32
    const float*  base  = (const float*)d_in[2];    // [15]  f32
    float* out = (float*)d_out;                     // [N,1] f32

    int n = in_sizes[0] / 4;   // rows
    int n_full = n / CHUNK;

    if (n_full > 0)
        sindy_kernel_exact<<<n_full, THREADS>>>((const f8*)big_u, coeff, base,
                                                (float2*)out);

    int tail_start = n_full * CHUNK;
    int tail = n - tail_start;
    if (tail > 0) {
        int tblocks = (tail + THREADS - 1) / THREADS;
        sindy_tail<<<tblocks, THREADS>>>(big_u, coeff, base, out, tail_start, n);
    }
}

// round 12
// speedup vs baseline: 1.0099x; 1.0099x over previous
#include <cuda_runtime.h>
#include <cstdint>

// Torch_SINDy streaming kernel, R12: TMA bulk-load staging.
// R7-R11: every LDG-based shape pins at ~73-76% DRAM. Hypothesis: cross-CTA
// L1tex wavefront-queue contention (spread model: oe*MLP_p1 >> 16). TMA
// cp.async.bulk loads the whole 16KB tile per block outside the L1tex queue;
// threads compute from smem (conflict-free LDS.128) and store coalesced.

#define THREADS 128
#define ITEMS 8
#define ROWS_PER_BLOCK (THREADS * ITEMS)          // 1024 rows
#define TILE_BYTES (ROWS_PER_BLOCK * 16)          // 16384 B

__device__ __forceinline__ uint32_t smem_u32(const void* p) {
    return (uint32_t)__cvta_generic_to_shared(p);
}

__device__ __forceinline__ float sindy_row(float4 v, const float* c) {
    float u  = v.x;
    float u2 = u * u;
    float u3 = u2 * u;
    float y = v.y, z = v.z, w = v.w;
    float r = u * c[0] + u2 * c[1] + u3 * c[2]
            + y * c[3] + z * c[4] + w * c[5];
    r += y * (u * c[6]  + u2 * c[7]  + u3 * c[8]);
    r += z * (u * c[9]  + u2 * c[10] + u3 * c[11]);
    r += w * (u * c[12] + u2 * c[13] + u3 * c[14]);
    return r;
}

__device__ __forceinline__ void load_coeffs(const float* __restrict__ coeff,
                                            const float* __restrict__ base,
                                            float* c) {
    const float4* c4 = (const float4*)coeff;
    const float4* b4 = (const float4*)base;
#pragma unroll
    for (int q = 0; q < 3; ++q) {
        float4 cv = __ldg(&c4[q]);
        float4 bv = __ldg(&b4[q]);
        c[q*4+0] = cv.x * bv.x;
        c[q*4+1] = cv.y * bv.y;
        c[q*4+2] = cv.z * bv.z;
        c[q*4+3] = cv.w * bv.w;
    }
#pragma unroll
    for (int q = 12; q < 15; ++q)
        c[q] = __ldg(&coeff[q]) * __ldg(&base[q]);
}

// Exact path: one 16KB bulk TMA load per block, compute from smem, plain
// coalesced stores. Grid covers n exactly (no guards).
__global__ void __launch_bounds__(THREADS)
sindy_kernel_exact(const float4* __restrict__ big_u,
                   const float*  __restrict__ coeff,
                   const float*  __restrict__ base,
                   float*        __restrict__ out) {
    __shared__ __align__(16) float4 buf[ROWS_PER_BLOCK];   // 16 KB
    __shared__ __align__(8) uint64_t mbar;

    uint32_t mbar_a = smem_u32(&mbar);

    if (threadIdx.x == 0) {
        asm volatile("mbarrier.init.shared.b64 [%0], 1;"
                     :: "r"(mbar_a) : "memory");
    }
    __syncthreads();

    if (threadIdx.x == 0) {
        asm volatile("mbarrier.arrive.expect_tx.shared.b64 _, [%0], %1;"
                     :: "r"(mbar_a), "r"((uint32_t)TILE_BYTES) : "memory");
        const float4* gsrc = big_u + (size_t)blockIdx.x * ROWS_PER_BLOCK;
        asm volatile(
            "cp.async.bulk.shared::cta.global.mbarrier::complete_tx::bytes "
            "[%0], [%1], %2, [%3];"
            :: "r"(smem_u32(buf)), "l"(gsrc), "r"((uint32_t)TILE_BYTES),
               "r"(mbar_a) : "memory");
    }

    // Coefficient loads + products overlap the in-flight bulk load.
    float c[15];
    load_coeffs(coeff, base, c);

    // Wait for tile arrival (parity 0).
    {
        uint32_t done;
        asm volatile(
            "{\n\t.reg .pred p;\n\t"
            "mbarrier.try_wait.parity.acquire.cta.shared::cta.b64 p, [%1], 0;\n\t"
            "selp.b32 %0, 1, 0, p;\n\t}"
            : "=r"(done) : "r"(mbar_a) : "memory");
        if (!done) {
            asm volatile(
                "{\n\t.reg .pred P1;\n\t"
                "WL_%=:\n\t"
                "mbarrier.try_wait.parity.acquire.cta.shared::cta.b64 P1, [%0], 0, 0x989680;\n\t"
                "@P1 bra.uni WD_%=;\n\t"
                "bra.uni WL_%=;\n\t"
                "WD_%=:\n\t}"
                :: "r"(mbar_a) : "memory");
        }
    }

    int base_i = blockIdx.x * ROWS_PER_BLOCK + threadIdx.x;
#pragma unroll
    for (int k = 0; k < ITEMS; ++k) {
        float4 v = buf[k * THREADS + threadIdx.x];   // conflict-free LDS.128
        out[base_i + k * THREADS] = sindy_row(v, c);
    }
}

// Guarded tail for arbitrary n (plain LDG path).
__global__ void __launch_bounds__(THREADS)
sindy_tail(const float4* __restrict__ big_u,
           const float*  __restrict__ coeff,
           const float*  __restrict__ base,
           float*        __restrict__ out,
           int start, int n) {
    float c[15];
    load_coeffs(coeff, base, c);
    int i = start + blockIdx.x * THREADS + threadIdx.x;
    if (i < n) {
        float4 v = __ldg(&big_u[i]);
        out[i] = sindy_row(v, c);
    }
}

extern "C" void kernel_launch(void* const* d_in, const int* in_sizes, int n_in,
                              void* d_out, int out_size) {
    const float4* big_u = (const float4*)d_in[0];   // [N,4] f32
    const float*  coeff = (const float*)d_in[1];    // [15]  f32
    const float*  base  = (const float*)d_in[2];    // [15]  f32
    float* out = (float*)d_out;                     // [N,1] f32

    int n = in_sizes[0] / 4;   // rows
    int n_full = n / ROWS_PER_BLOCK;

    if (n_full > 0)
        sindy_kernel_exact<<<n_full, THREADS>>>(big_u, coeff, base, out);

    int tail_start = n_full * ROWS_PER_BLOCK;
    int tail = n - tail_start;
    if (tail > 0) {
        int tblocks = (tail + THREADS - 1) / THREADS;
        sindy_tail<<<tblocks, THREADS>>>(big_u, coeff, base, out, tail_start, n);
    }
}

// round 13
// speedup vs baseline: 1.0612x; 1.0508x over previous
#include <cuda_runtime.h>

// Torch_SINDy streaming kernel, R13 (final-form candidate).
// Evidence R4-R12: persistent/work-steal/packed-store/LDG.256/cp.async/TMA
// all regress; plateau ~76% DRAM = HBM read/write-mix ceiling for this
// 16B-in/4B-out stream. Champion shape = one-shot, block-strided MLP=8
// front batch, __ldcs/__stcs (R7, 24.0us kernel).
// R13: THREADS 128->64 — continue the only winning trend (finer block
// granularity: smaller tail fraction, better SM packing; warp budget
// unchanged at ~52/SM).

#define ITEMS 8
#define THREADS 64
#define CHUNK (THREADS * ITEMS)   // 512 rows per block

__device__ __forceinline__ float sindy_row(float4 v, const float* c) {
    float u  = v.x;
    float u2 = u * u;
    float u3 = u2 * u;
    float y = v.y, z = v.z, w = v.w;
    float r = u * c[0] + u2 * c[1] + u3 * c[2]
            + y * c[3] + z * c[4] + w * c[5];
    r += y * (u * c[6]  + u2 * c[7]  + u3 * c[8]);
    r += z * (u * c[9]  + u2 * c[10] + u3 * c[11]);
    r += w * (u * c[12] + u2 * c[13] + u3 * c[14]);
    return r;
}

__device__ __forceinline__ void load_coeffs(const float* __restrict__ coeff,
                                            const float* __restrict__ base,
                                            float* c) {
    const float4* c4 = (const float4*)coeff;
    const float4* b4 = (const float4*)base;
#pragma unroll
    for (int q = 0; q < 3; ++q) {
        float4 cv = __ldg(&c4[q]);
        float4 bv = __ldg(&b4[q]);
        c[q*4+0] = cv.x * bv.x;
        c[q*4+1] = cv.y * bv.y;
        c[q*4+2] = cv.z * bv.z;
        c[q*4+3] = cv.w * bv.w;
    }
#pragma unroll
    for (int q = 12; q < 15; ++q)
        c[q] = __ldg(&coeff[q]) * __ldg(&base[q]);
}

// Exact path: grid covers n exactly, no guards. 8 front-batched coalesced
// LDG.128 first; coeff loads complete under their DRAM shadow.
__global__ void __launch_bounds__(THREADS)
sindy_kernel_exact(const float4* __restrict__ big_u,
                   const float*  __restrict__ coeff,
                   const float*  __restrict__ base,
                   float*        __restrict__ out) {
    int base_i = blockIdx.x * CHUNK + threadIdx.x;

    float4 v[ITEMS];
#pragma unroll
    for (int k = 0; k < ITEMS; ++k)
        v[k] = __ldcs(&big_u[base_i + k * THREADS]);

    float c[15];
    load_coeffs(coeff, base, c);

#pragma unroll
    for (int k = 0; k < ITEMS; ++k)
        __stcs(&out[base_i + k * THREADS], sindy_row(v[k], c));
}

// Guarded tail for arbitrary n.
__global__ void __launch_bounds__(THREADS)
sindy_tail(const float4* __restrict__ big_u,
           const float*  __restrict__ coeff,
           const float*  __restrict__ base,
           float*        __restrict__ out,
           int start, int n) {
    float c[15];
    load_coeffs(coeff, base, c);
    int i = start + blockIdx.x * THREADS + threadIdx.x;
    if (i < n) {
        float4 v = __ldcs(&big_u[i]);
        __stcs(&out[i], sindy_row(v, c));
    }
}

extern "C" void kernel_launch(void* const* d_in, const int* in_sizes, int n_in,
                              void* d_out, int out_size) {
    const float4* big_u = (const float4*)d_in[0];   // [N,4] f32
    const float*  coeff = (const float*)d_in[1];    // [15]  f32
    const float*  base  = (const float*)d_in[2];    // [15]  f32
    float* out = (float*)d_out;                     // [N,1] f32

    int n = in_sizes[0] / 4;   // rows
    int n_full = n / CHUNK;

    if (n_full > 0)
        sindy_kernel_exact<<<n_full, THREADS>>>(big_u, coeff, base, out);

    int tail_start = n_full * CHUNK;
    int tail = n - tail_start;
    if (tail > 0) {
        int tblocks = (tail + THREADS - 1) / THREADS;
        sindy_tail<<<tblocks, THREADS>>>(big_u, coeff, base, out, tail_start, n);
    }
}

// round 14
// speedup vs baseline: 1.0850x; 1.0224x over previous
#include <cuda_runtime.h>

// Torch_SINDy streaming kernel — FINAL (champion consolidation).
// 160MiB single-pass stream (16B in / 4B out per row). Search record
// (R3-R13): one-shot grid + 128-thread blocks + block-strided MLP=8
// front-batched LDG.128 is optimal (24.0us kernel, 76.5% DRAM, ~6.06TB/s).
// Persistent loops, work-stealing, MLP=16, packed stores, LDG.256,
// cp.async and TMA staging all regressed to 70-73% — the ~76% plateau is
// the HBM read/write-turnaround roofline for this 4:1 mix.
// Ordering: data loads issue first; coefficient loads + products complete
// under their DRAM shadow.

#define ITEMS 8
#define THREADS 128
#define CHUNK (THREADS * ITEMS)   // 1024 rows per block

__device__ __forceinline__ float sindy_row(float4 v, const float* c) {
    float u  = v.x;
    float u2 = u * u;
    float u3 = u2 * u;
    float y = v.y, z = v.z, w = v.w;
    float r = u * c[0] + u2 * c[1] + u3 * c[2]
            + y * c[3] + z * c[4] + w * c[5];
    r += y * (u * c[6]  + u2 * c[7]  + u3 * c[8]);
    r += z * (u * c[9]  + u2 * c[10] + u3 * c[11]);
    r += w * (u * c[12] + u2 * c[13] + u3 * c[14]);
    return r;
}

__device__ __forceinline__ void load_coeffs(const float* __restrict__ coeff,
                                            const float* __restrict__ base,
                                            float* c) {
    const float4* c4 = (const float4*)coeff;
    const float4* b4 = (const float4*)base;
#pragma unroll
    for (int q = 0; q < 3; ++q) {
        float4 cv = __ldg(&c4[q]);
        float4 bv = __ldg(&b4[q]);
        c[q*4+0] = cv.x * bv.x;
        c[q*4+1] = cv.y * bv.y;
        c[q*4+2] = cv.z * bv.z;
        c[q*4+3] = cv.w * bv.w;
    }
#pragma unroll
    for (int q = 12; q < 15; ++q)
        c[q] = __ldg(&coeff[q]) * __ldg(&base[q]);
}

// Exact path: grid covers n exactly, no guards. 8 front-batched coalesced
// LDG.128.cs first; coefficient loads complete under their DRAM shadow.
__global__ void __launch_bounds__(THREADS)
sindy_kernel_exact(const float4* __restrict__ big_u,
                   const float*  __restrict__ coeff,
                   const float*  __restrict__ base,
                   float*        __restrict__ out) {
    int base_i = blockIdx.x * CHUNK + threadIdx.x;

    float4 v[ITEMS];
#pragma unroll
    for (int k = 0; k < ITEMS; ++k)
        v[k] = __ldcs(&big_u[base_i + k * THREADS]);

    float c[15];
    load_coeffs(coeff, base, c);

#pragma unroll
    for (int k = 0; k < ITEMS; ++k)
        __stcs(&out[base_i + k * THREADS], sindy_row(v[k], c));
}

// Guarded tail for arbitrary n.
__global__ void __launch_bounds__(THREADS)
sindy_tail(const float4* __restrict__ big_u,
           const float*  __restrict__ coeff,
           const float*  __restrict__ base,
           float*        __restrict__ out,
           int start, int n) {
    float c[15];
    load_coeffs(coeff, base, c);
    int i = start + blockIdx.x * THREADS + threadIdx.x;
    if (i < n) {
        float4 v = __ldcs(&big_u[i]);
        __stcs(&out[i], sindy_row(v, c));
    }
}

extern "C" void kernel_launch(void* const* d_in, const int* in_sizes, int n_in,
                              void* d_out, int out_size) {
    const float4* big_u = (const float4*)d_in[0];   // [N,4] f32
    const float*  coeff = (const float*)d_in[1];    // [15]  f32
    const float*  base  = (const float*)d_in[2];    // [15]  f32
    float* out = (float*)d_out;                     // [N,1] f32

    int n = in_sizes[0] / 4;   // rows
    int n_full = n / CHUNK;

    if (n_full > 0)
        sindy_kernel_exact<<<n_full, THREADS>>>(big_u, coeff, base, out);

    int tail_start = n_full * CHUNK;
    int tail = n - tail_start;
    if (tail > 0) {
        int tblocks = (tail + THREADS - 1) / THREADS;
        sindy_tail<<<tblocks, THREADS>>>(big_u, coeff, base, out, tail_start, n);
    }
}